// round 5
// baseline (speedup 1.0000x reference)
#include <cuda_runtime.h>
#include <cstdint>

// Problem constants
#define B_ 4
#define T_ 2048
#define C_ 1024
#define H_ 16
#define D_ 64
#define M_ (B_ * T_)   // 8192 rows

// Scratch (allocation-free rule: __device__ globals)
__device__ float g_Q[(size_t)B_ * H_ * T_ * D_];   // [b,h,t,d] 32 MB
__device__ float g_K[(size_t)B_ * H_ * T_ * D_];
__device__ float g_V[(size_t)B_ * H_ * T_ * D_];
__device__ float g_Y[(size_t)M_ * C_];             // attention out, [b*T+t, h*D+d]

// ---------------------------------------------------------------------------
// GEMM body: out = A[M,K] @ W[N,K]^T (+ bias). M=8192, N=K=1024.
// BM=BN=128, BK=16, 256 threads, 8x8 microtile (split 4+4 rows/cols).
// MODE 0: plain [M,N] + bias. MODE 1: write split-head layout [b,h,t,d].
// ---------------------------------------------------------------------------
template <int MODE>
__device__ __forceinline__
void gemm_body(const float* __restrict__ A, const float* __restrict__ W,
               const float* __restrict__ bias, float* __restrict__ out)
{
    const int K = C_;
    __shared__ __align__(16) float As[16][132];   // transposed: As[k][m]
    __shared__ __align__(16) float Bs[16][132];   // transposed: Bs[k][n]

    const int m0 = blockIdx.y * 128;
    const int n0 = blockIdx.x * 128;
    const int t  = threadIdx.x;
    const int ty = t >> 4;          // 0..15  (M groups)
    const int tx = t & 15;          // 0..15  (N groups)

    float acc[8][8];
#pragma unroll
    for (int i = 0; i < 8; i++)
#pragma unroll
        for (int j = 0; j < 8; j++) acc[i][j] = 0.0f;

    for (int k0 = 0; k0 < K; k0 += 16) {
#pragma unroll
        for (int rep = 0; rep < 2; rep++) {
            int f   = t + rep * 256;       // 0..511 float4 slots
            int row = f >> 2;              // 0..127
            int kq  = f & 3;               // 0..3
            float4 va = *(const float4*)&A[(size_t)(m0 + row) * K + k0 + kq * 4];
            As[kq * 4 + 0][row] = va.x;
            As[kq * 4 + 1][row] = va.y;
            As[kq * 4 + 2][row] = va.z;
            As[kq * 4 + 3][row] = va.w;
            float4 vb = *(const float4*)&W[(size_t)(n0 + row) * K + k0 + kq * 4];
            Bs[kq * 4 + 0][row] = vb.x;
            Bs[kq * 4 + 1][row] = vb.y;
            Bs[kq * 4 + 2][row] = vb.z;
            Bs[kq * 4 + 3][row] = vb.w;
        }
        __syncthreads();

#pragma unroll
        for (int kk = 0; kk < 16; kk++) {
            float a[8], b[8];
            *(float4*)&a[0] = *(const float4*)&As[kk][ty * 4];
            *(float4*)&a[4] = *(const float4*)&As[kk][ty * 4 + 64];
            *(float4*)&b[0] = *(const float4*)&Bs[kk][tx * 4];
            *(float4*)&b[4] = *(const float4*)&Bs[kk][tx * 4 + 64];
#pragma unroll
            for (int i = 0; i < 8; i++)
#pragma unroll
                for (int j = 0; j < 8; j++)
                    acc[i][j] = fmaf(a[i], b[j], acc[i][j]);
        }
        __syncthreads();
    }

    // Epilogue
#pragma unroll
    for (int i = 0; i < 8; i++) {
        int r    = (i < 4) ? (ty * 4 + i) : (64 + ty * 4 + (i - 4));
        int grow = m0 + r;
#pragma unroll
        for (int jh = 0; jh < 2; jh++) {
            int c0   = jh * 64 + tx * 4;
            int gcol = n0 + c0;
            float4 v = make_float4(acc[i][jh * 4 + 0], acc[i][jh * 4 + 1],
                                   acc[i][jh * 4 + 2], acc[i][jh * 4 + 3]);
            if (MODE == 0) {
                float4 bb = *(const float4*)&bias[gcol];
                v.x += bb.x; v.y += bb.y; v.z += bb.z; v.w += bb.w;
                *(float4*)&out[(size_t)grow * C_ + gcol] = v;
            } else {
                int head = gcol >> 6;       // D=64
                int d    = gcol & 63;
                int bidx = grow >> 11;      // T=2048
                int tt   = grow & (T_ - 1);
                *(float4*)&out[(((size_t)bidx * H_ + head) * T_ + tt) * D_ + d] = v;
            }
        }
    }
}

// Fused Q/K/V projection: blockIdx.z selects weight + destination.
// 1536 CTAs in one launch -> 5.2 waves instead of 3 x 1.73 (tail amortized).
__global__ __launch_bounds__(256, 2)
void gemm_qkv_kernel(const float* __restrict__ X,
                     const float* __restrict__ Wq, const float* __restrict__ Wk,
                     const float* __restrict__ Wv,
                     float* __restrict__ Q, float* __restrict__ K,
                     float* __restrict__ V)
{
    const float* W = (blockIdx.z == 0) ? Wq : (blockIdx.z == 1) ? Wk : Wv;
    float*     out = (blockIdx.z == 0) ? Q  : (blockIdx.z == 1) ? K  : V;
    gemm_body<1>(X, W, nullptr, out);
}

// Output projection with bias.
__global__ __launch_bounds__(256, 2)
void gemm_out_kernel(const float* __restrict__ A, const float* __restrict__ W,
                     const float* __restrict__ bias, float* __restrict__ out)
{
    gemm_body<0>(A, W, bias, out);
}

// ---------------------------------------------------------------------------
// Flash attention (causal). One block per (q-tile of 128 rows, b*h).
// BKV=64 per inner step. Online softmax. All fp32.
// ---------------------------------------------------------------------------
__global__ __launch_bounds__(256, 2)
void attn_kernel(float* __restrict__ Y)
{
    extern __shared__ __align__(16) float sm[];
    float* Qs     = sm;                  // [128][65]
    float* Ks     = Qs + 128 * 65;       // [64][65]
    float* Vs     = Ks + 64 * 65;        // [64][68]
    float* sP     = Vs + 64 * 68;        // [128][68]
    float* m_s    = sP + 128 * 68;       // [128]
    float* l_s    = m_s + 128;           // [128]
    float* corr_s = l_s + 128;           // [128]
    float* red    = corr_s + 128;        // [256]

    const int t  = threadIdx.x;
    const int ty = t >> 4;               // 0..15
    const int tx = t & 15;               // 0..15
    const int bh = blockIdx.y;
    const int qi = (int)(gridDim.x - 1 - blockIdx.x);  // big tiles first
    const int qbase = qi * 128;

    const float* Qg = g_Q + (size_t)bh * T_ * D_;
    const float* Kg = g_K + (size_t)bh * T_ * D_;
    const float* Vg = g_V + (size_t)bh * T_ * D_;

    if (t < 128) { m_s[t] = -1e30f; l_s[t] = 0.0f; }

    // Load Q tile [128][64] into padded smem
#pragma unroll
    for (int rep = 0; rep < 8; rep++) {
        int f   = t + rep * 256;         // 0..2047 float4 slots
        int row = f >> 4;                // 0..127
        int dq  = f & 15;                // 0..15
        float4 v = *(const float4*)&Qg[(size_t)(qbase + row) * D_ + dq * 4];
        Qs[row * 65 + dq * 4 + 0] = v.x;
        Qs[row * 65 + dq * 4 + 1] = v.y;
        Qs[row * 65 + dq * 4 + 2] = v.z;
        Qs[row * 65 + dq * 4 + 3] = v.w;
    }

    float o[8][4];
#pragma unroll
    for (int i = 0; i < 8; i++)
#pragma unroll
        for (int j = 0; j < 4; j++) o[i][j] = 0.0f;

    const int kmax = 2 * qi + 1;         // BQ = 2*BKV
    for (int kj = 0; kj <= kmax; kj++) {
        const int kbase = kj * 64;
        __syncthreads();                 // prev tile fully consumed (also covers Q load)

        // Load K, V tiles (64x64 each)
#pragma unroll
        for (int rep = 0; rep < 4; rep++) {
            int f   = t + rep * 256;     // 0..1023 float4 slots
            int row = f >> 4;            // 0..63
            int dq  = f & 15;
            float4 vk = *(const float4*)&Kg[(size_t)(kbase + row) * D_ + dq * 4];
            Ks[row * 65 + dq * 4 + 0] = vk.x;
            Ks[row * 65 + dq * 4 + 1] = vk.y;
            Ks[row * 65 + dq * 4 + 2] = vk.z;
            Ks[row * 65 + dq * 4 + 3] = vk.w;
            float4 vv = *(const float4*)&Vg[(size_t)(kbase + row) * D_ + dq * 4];
            *(float4*)&Vs[row * 68 + dq * 4] = vv;
        }
        __syncthreads();

        // S = Q @ K^T  (128x64), (4+4)x4 microtile per thread
        float s[8][4];
#pragma unroll
        for (int i = 0; i < 8; i++)
#pragma unroll
            for (int j = 0; j < 4; j++) s[i][j] = 0.0f;

#pragma unroll 8
        for (int d = 0; d < 64; d++) {
            float a[8], bk[4];
#pragma unroll
            for (int i = 0; i < 4; i++) {
                a[i]     = Qs[(ty * 4 + i) * 65 + d];
                a[i + 4] = Qs[(64 + ty * 4 + i) * 65 + d];
            }
#pragma unroll
            for (int j = 0; j < 4; j++) bk[j] = Ks[(tx * 4 + j) * 65 + d];
#pragma unroll
            for (int i = 0; i < 8; i++)
#pragma unroll
                for (int j = 0; j < 4; j++)
                    s[i][j] = fmaf(a[i], bk[j], s[i][j]);
        }

        // Scale + causal mask + write to sP (row-major, pad 68)
#pragma unroll
        for (int i = 0; i < 8; i++) {
            int rr = (i < 4) ? (ty * 4 + i) : (64 + ty * 4 + (i - 4));
            int rg = qbase + rr;
            float4 v;
            v.x = (kbase + tx * 4 + 0 > rg) ? -1e30f : s[i][0] * 0.125f;
            v.y = (kbase + tx * 4 + 1 > rg) ? -1e30f : s[i][1] * 0.125f;
            v.z = (kbase + tx * 4 + 2 > rg) ? -1e30f : s[i][2] * 0.125f;
            v.w = (kbase + tx * 4 + 3 > rg) ? -1e30f : s[i][3] * 0.125f;
            *(float4*)&sP[rr * 68 + tx * 4] = v;
        }
        __syncthreads();                 // (A) S visible

        // Online softmax: 2 threads per row
        {
            int r = t >> 1, q = t & 1;
            float* rowp = &sP[r * 68 + q * 32];
            float lmax = -1e30f;
#pragma unroll
            for (int c = 0; c < 32; c++) lmax = fmaxf(lmax, rowp[c]);
            red[r * 2 + q] = lmax;
            __syncthreads();             // (B)
            float m_old = m_s[r];
            float m_new = fmaxf(m_old, fmaxf(red[r * 2], red[r * 2 + 1]));
            float lsum = 0.0f;
#pragma unroll
            for (int c = 0; c < 32; c++) {
                float p = __expf(rowp[c] - m_new);
                rowp[c] = p;
                lsum += p;
            }
            __syncthreads();             // (C) all max-reads of red done
            red[r * 2 + q] = lsum;
            if (q == 0) corr_s[r] = __expf(m_old - m_new);
            __syncthreads();             // (D)
            if (q == 0) {
                l_s[r] = l_s[r] * corr_s[r] + red[r * 2] + red[r * 2 + 1];
                m_s[r] = m_new;
            }
        }

        // Rescale O, then O += P @ V
#pragma unroll
        for (int i = 0; i < 8; i++) {
            int rr = (i < 4) ? (ty * 4 + i) : (64 + ty * 4 + (i - 4));
            float cr = corr_s[rr];
#pragma unroll
            for (int j = 0; j < 4; j++) o[i][j] *= cr;
        }

#pragma unroll 8
        for (int j0 = 0; j0 < 64; j0++) {
            float a[8];
#pragma unroll
            for (int i = 0; i < 4; i++) {
                a[i]     = sP[(ty * 4 + i) * 68 + j0];
                a[i + 4] = sP[(64 + ty * 4 + i) * 68 + j0];
            }
            float4 bv = *(const float4*)&Vs[j0 * 68 + tx * 4];
#pragma unroll
            for (int i = 0; i < 8; i++) {
                o[i][0] = fmaf(a[i], bv.x, o[i][0]);
                o[i][1] = fmaf(a[i], bv.y, o[i][1]);
                o[i][2] = fmaf(a[i], bv.z, o[i][2]);
                o[i][3] = fmaf(a[i], bv.w, o[i][3]);
            }
        }
    }

    __syncthreads();                     // final l_s visible to all

    const int b = bh >> 4;               // H=16
    const int h = bh & 15;
#pragma unroll
    for (int i = 0; i < 8; i++) {
        int rr  = (i < 4) ? (ty * 4 + i) : (64 + ty * 4 + (i - 4));
        float inv = 1.0f / l_s[rr];
        int tg  = qbase + rr;
        float4 v = make_float4(o[i][0] * inv, o[i][1] * inv,
                               o[i][2] * inv, o[i][3] * inv);
        *(float4*)&Y[((size_t)b * T_ + tg) * C_ + h * 64 + tx * 4] = v;
    }
}

// ---------------------------------------------------------------------------
extern "C" void kernel_launch(void* const* d_in, const int* in_sizes, int n_in,
                              void* d_out, int out_size)
{
    const float* X  = (const float*)d_in[0];
    const float* Wq = (const float*)d_in[1];
    const float* Wk = (const float*)d_in[2];
    const float* Wv = (const float*)d_in[3];
    const float* Wo = (const float*)d_in[4];
    const float* bo = (const float*)d_in[5];
    float* out = (float*)d_out;

    float *qp, *kp, *vp, *yp;
    cudaGetSymbolAddress((void**)&qp, g_Q);
    cudaGetSymbolAddress((void**)&kp, g_K);
    cudaGetSymbolAddress((void**)&vp, g_V);
    cudaGetSymbolAddress((void**)&yp, g_Y);

    // Fused Q/K/V projections: one launch, 1536 CTAs
    gemm_qkv_kernel<<<dim3(C_ / 128, M_ / 128, 3), 256>>>(X, Wq, Wk, Wv, qp, kp, vp);

    const size_t smem = (size_t)(128 * 65 + 64 * 65 + 64 * 68 + 128 * 68 +
                                 128 * 3 + 256) * sizeof(float);  // ~102 KB
    cudaFuncSetAttribute((const void*)attn_kernel,
                         cudaFuncAttributeMaxDynamicSharedMemorySize, (int)smem);
    attn_kernel<<<dim3(T_ / 128, B_ * H_), 256, smem>>>(yp);

    gemm_out_kernel<<<dim3(C_ / 128, M_ / 128), 256>>>(yp, Wo, bo, out);
}

// round 7
// speedup vs baseline: 1.5210x; 1.5210x over previous
#include <cuda_runtime.h>
#include <cuda_bf16.h>
#include <cstdint>

// Problem constants
#define B_ 4
#define T_ 2048
#define C_ 1024
#define H_ 16
#define D_ 64
#define M_ (B_ * T_)   // 8192 rows

// ---------------------------------------------------------------------------
// Scratch (allocation-free rule: __device__ globals)
// ---------------------------------------------------------------------------
__device__ float g_Q[(size_t)B_ * H_ * T_ * D_];   // [b,h,t,d]
__device__ float g_K[(size_t)B_ * H_ * T_ * D_];
__device__ float g_V[(size_t)B_ * H_ * T_ * D_];
__device__ float g_Y[(size_t)M_ * C_];             // attention out [b*T+t, h*D+d]

__device__ __align__(16) __nv_bfloat16 g_Xhi[(size_t)M_ * C_];
__device__ __align__(16) __nv_bfloat16 g_Xlo[(size_t)M_ * C_];
__device__ __align__(16) __nv_bfloat16 g_Wh[(size_t)3 * C_ * C_];   // Wq,Wk,Wv hi
__device__ __align__(16) __nv_bfloat16 g_Wl[(size_t)3 * C_ * C_];   // Wq,Wk,Wv lo
__device__ __align__(16) __nv_bfloat16 g_Wohi[(size_t)C_ * C_];
__device__ __align__(16) __nv_bfloat16 g_Wolo[(size_t)C_ * C_];
__device__ __align__(16) __nv_bfloat16 g_Yhi[(size_t)M_ * C_];
__device__ __align__(16) __nv_bfloat16 g_Ylo[(size_t)M_ * C_];

// ---------------------------------------------------------------------------
// fp32 -> bf16 hi/lo split (elementwise, vectorized by 4)
// ---------------------------------------------------------------------------
__global__ __launch_bounds__(256)
void cvt_kernel(const float* __restrict__ in, __nv_bfloat16* __restrict__ hi,
                __nv_bfloat16* __restrict__ lo, int n4)
{
    int i = blockIdx.x * 256 + threadIdx.x;
    if (i >= n4) return;
    float4 v = ((const float4*)in)[i];
    __nv_bfloat16 h0 = __float2bfloat16_rn(v.x);
    __nv_bfloat16 h1 = __float2bfloat16_rn(v.y);
    __nv_bfloat16 h2 = __float2bfloat16_rn(v.z);
    __nv_bfloat16 h3 = __float2bfloat16_rn(v.w);
    __nv_bfloat16 l0 = __float2bfloat16_rn(v.x - __bfloat162float(h0));
    __nv_bfloat16 l1 = __float2bfloat16_rn(v.y - __bfloat162float(h1));
    __nv_bfloat16 l2 = __float2bfloat16_rn(v.z - __bfloat162float(h2));
    __nv_bfloat16 l3 = __float2bfloat16_rn(v.w - __bfloat162float(h3));
    ((__nv_bfloat162*)hi)[2 * i]     = __halves2bfloat162(h0, h1);
    ((__nv_bfloat162*)hi)[2 * i + 1] = __halves2bfloat162(h2, h3);
    ((__nv_bfloat162*)lo)[2 * i]     = __halves2bfloat162(l0, l1);
    ((__nv_bfloat162*)lo)[2 * i + 1] = __halves2bfloat162(l2, l3);
}

// ---------------------------------------------------------------------------
// HMMA bf16 GEMM with hi/lo split as extended-K:
//   out[M,N] = A @ W^T over K_eff = 3*1024, segment s selects
//   s0:(Ahi,Whi)  s1:(Ahi,Wlo)  s2:(Alo,Whi)
// Tile: BM=128, BN=128, BK=64 bf16 (128B rows, XOR-swizzled, ldmatrix-ready).
// 256 threads = 8 warps (4 M x 2 N), warp tile 32x64 = 2x8 m16n8k16.
// cp.async double-buffered (2 x 32KB stages).
// MODE 0: [M,N] + bias.   MODE 1: split-head [b,h,t,d].
// ---------------------------------------------------------------------------
#define NKCH 48          // 3072 / 64
#define STAGE_B 32768    // A(16KB) + B(16KB)

__device__ __forceinline__ uint32_t smem_u32(const void* p) {
    uint32_t a;
    asm("{ .reg .u64 t; cvta.to.shared.u64 t, %1; cvt.u32.u64 %0, t; }"
        : "=r"(a) : "l"(p));
    return a;
}

#define CP_ASYNC16(dst, src) \
    asm volatile("cp.async.cg.shared.global [%0], [%1], 16;" \
                 :: "r"(dst), "l"(src) : "memory")
#define CP_COMMIT()  asm volatile("cp.async.commit_group;" ::: "memory")
#define CP_WAIT(n)   asm volatile("cp.async.wait_group %0;" :: "n"(n) : "memory")

#define LDSM_X4(r0, r1, r2, r3, addr) \
    asm volatile("ldmatrix.sync.aligned.m8n8.x4.shared.b16 {%0,%1,%2,%3}, [%4];" \
                 : "=r"(r0), "=r"(r1), "=r"(r2), "=r"(r3) : "r"(addr))

#define MMA16816(d, a, b0, b1) \
    asm volatile("mma.sync.aligned.m16n8k16.row.col.f32.bf16.bf16.f32 " \
                 "{%0,%1,%2,%3}, {%4,%5,%6,%7}, {%8,%9}, {%0,%1,%2,%3};" \
                 : "+f"((d)[0]), "+f"((d)[1]), "+f"((d)[2]), "+f"((d)[3]) \
                 : "r"((a)[0]), "r"((a)[1]), "r"((a)[2]), "r"((a)[3]), \
                   "r"(b0), "r"(b1))

__device__ __forceinline__
void issue_chunk(uint32_t sbase, const __nv_bfloat16* __restrict__ Aseg,
                 const __nv_bfloat16* __restrict__ Bseg,
                 int m0, int n0, int k_in, int t)
{
#pragma unroll
    for (int rep = 0; rep < 4; rep++) {
        int idx = t + rep * 256;        // 0..1023 16B slots per tile
        int r = idx >> 3, s = idx & 7;
        uint32_t dstA = sbase + r * 128 + ((s ^ (r & 7)) << 4);
        const void* srcA = Aseg + (size_t)(m0 + r) * C_ + k_in + s * 8;
        CP_ASYNC16(dstA, srcA);
        const void* srcB = Bseg + (size_t)(n0 + r) * C_ + k_in + s * 8;
        CP_ASYNC16(dstA + 16384, srcB);
    }
}

template <int MODE>
__device__ __forceinline__
void hmma_gemm_body(const __nv_bfloat16* __restrict__ Ahi,
                    const __nv_bfloat16* __restrict__ Alo,
                    const __nv_bfloat16* __restrict__ Whi,
                    const __nv_bfloat16* __restrict__ Wlo,
                    const float* __restrict__ bias, float* __restrict__ out)
{
    extern __shared__ __align__(128) char sm[];
    const uint32_t sm0 = smem_u32(sm);
    const int t    = threadIdx.x;
    const int lane = t & 31;
    const int w    = t >> 5;
    const int wm   = w & 3;             // 0..3 -> m offset 32*wm
    const int wn   = w >> 2;            // 0..1 -> n offset 64*wn
    const int m0   = blockIdx.y * 128;
    const int n0   = blockIdx.x * 128;

    // ldmatrix per-lane base offsets (within a stage)
    const int l4 = lane >> 4;           // 0/1 -> k8 half
    uint32_t baseA[2], baseB[4];
#pragma unroll
    for (int mt = 0; mt < 2; mt++) {
        int m_l = wm * 32 + mt * 16 + ((lane >> 3) & 1) * 8 + (lane & 7);
        baseA[mt] = m_l * 128 + (((m_l & 7) ^ l4) << 4);
    }
#pragma unroll
    for (int j = 0; j < 4; j++) {
        int n_l = wn * 64 + j * 16 + ((lane >> 3) & 1) * 8 + (lane & 7);
        baseB[j] = 16384 + n_l * 128 + (((n_l & 7) ^ l4) << 4);
    }

    float acc[2][8][4];
#pragma unroll
    for (int mt = 0; mt < 2; mt++)
#pragma unroll
        for (int nt = 0; nt < 8; nt++)
#pragma unroll
            for (int e = 0; e < 4; e++) acc[mt][nt][e] = 0.0f;

    // prologue: chunk 0 -> stage 0
    issue_chunk(sm0, Ahi, Whi, m0, n0, 0, t);
    CP_COMMIT();

    for (int kc = 0; kc < NKCH; kc++) {
        __syncthreads();                 // prior compute done before overwrite
        if (kc + 1 < NKCH) {
            int kn = kc + 1;
            const __nv_bfloat16* Aseg = (kn < 32) ? Ahi : Alo;
            const __nv_bfloat16* Bseg = (kn < 16) ? Whi : (kn < 32 ? Wlo : Whi);
            issue_chunk(sm0 + ((kn & 1) ? STAGE_B : 0), Aseg, Bseg,
                        m0, n0, (kn & 15) * 64, t);
            CP_COMMIT();
            CP_WAIT(1);                  // chunk kc landed
        } else {
            CP_WAIT(0);
        }
        __syncthreads();

        const uint32_t sbase = sm0 + ((kc & 1) ? STAGE_B : 0);
#pragma unroll
        for (int kk = 0; kk < 4; kk++) {
            uint32_t a[2][4], b[4][4];
#pragma unroll
            for (int mt = 0; mt < 2; mt++)
                LDSM_X4(a[mt][0], a[mt][1], a[mt][2], a[mt][3],
                        sbase + (baseA[mt] ^ (kk << 5)));
#pragma unroll
            for (int j = 0; j < 4; j++)
                LDSM_X4(b[j][0], b[j][1], b[j][2], b[j][3],
                        sbase + (baseB[j] ^ (kk << 5)));
#pragma unroll
            for (int mt = 0; mt < 2; mt++)
#pragma unroll
                for (int nt = 0; nt < 8; nt++)
                    MMA16816(acc[mt][nt], a[mt],
                             b[nt >> 1][nt & 1], b[nt >> 1][(nt & 1) + 2]);
        }
    }

    // Epilogue: c-frag lane (m = lane/4 (+8), n = 2*(lane%4) (+1))
    const int qrow = lane >> 2;
    const int qcol = (lane & 3) * 2;
#pragma unroll
    for (int mt = 0; mt < 2; mt++) {
#pragma unroll
        for (int half = 0; half < 2; half++) {
            const int grow = m0 + wm * 32 + mt * 16 + half * 8 + qrow;
#pragma unroll
            for (int nt = 0; nt < 8; nt++) {
                const int gcol = n0 + wn * 64 + nt * 8 + qcol;
                float2 v = make_float2(acc[mt][nt][half * 2],
                                       acc[mt][nt][half * 2 + 1]);
                if (MODE == 0) {
                    v.x += bias[gcol];
                    v.y += bias[gcol + 1];
                    *(float2*)&out[(size_t)grow * C_ + gcol] = v;
                } else {
                    const int head = gcol >> 6, d = gcol & 63;
                    const int bb = grow >> 11, tt = grow & (T_ - 1);
                    *(float2*)&out[(((size_t)bb * H_ + head) * T_ + tt) * D_ + d] = v;
                }
            }
        }
    }
}

__global__ __launch_bounds__(256)
void tc_gemm_qkv(const __nv_bfloat16* __restrict__ Xhi,
                 const __nv_bfloat16* __restrict__ Xlo,
                 const __nv_bfloat16* __restrict__ Wh,
                 const __nv_bfloat16* __restrict__ Wl,
                 float* __restrict__ Q, float* __restrict__ K, float* __restrict__ V)
{
    const int z = blockIdx.z;
    const __nv_bfloat16* wh = Wh + (size_t)z * C_ * C_;
    const __nv_bfloat16* wl = Wl + (size_t)z * C_ * C_;
    float* o = (z == 0) ? Q : (z == 1) ? K : V;
    hmma_gemm_body<1>(Xhi, Xlo, wh, wl, nullptr, o);
}

__global__ __launch_bounds__(256)
void tc_gemm_out(const __nv_bfloat16* __restrict__ Yhi,
                 const __nv_bfloat16* __restrict__ Ylo,
                 const __nv_bfloat16* __restrict__ Wh,
                 const __nv_bfloat16* __restrict__ Wl,
                 const float* __restrict__ bias, float* __restrict__ out)
{
    hmma_gemm_body<0>(Yhi, Ylo, Wh, Wl, bias, out);
}

// ---------------------------------------------------------------------------
// Flash attention (causal), fp32 — unchanged from passing R5 kernel.
// ---------------------------------------------------------------------------
__global__ __launch_bounds__(256, 2)
void attn_kernel(float* __restrict__ Y)
{
    extern __shared__ __align__(16) float smf[];
    float* Qs     = smf;                 // [128][65]
    float* Ks     = Qs + 128 * 65;       // [64][65]
    float* Vs     = Ks + 64 * 65;        // [64][68]
    float* sP     = Vs + 64 * 68;        // [128][68]
    float* m_s    = sP + 128 * 68;       // [128]
    float* l_s    = m_s + 128;
    float* corr_s = l_s + 128;
    float* red    = corr_s + 128;        // [256]

    const int t  = threadIdx.x;
    const int ty = t >> 4;
    const int tx = t & 15;
    const int bh = blockIdx.y;
    const int qi = (int)(gridDim.x - 1 - blockIdx.x);
    const int qbase = qi * 128;

    const float* Qg = g_Q + (size_t)bh * T_ * D_;
    const float* Kg = g_K + (size_t)bh * T_ * D_;
    const float* Vg = g_V + (size_t)bh * T_ * D_;

    if (t < 128) { m_s[t] = -1e30f; l_s[t] = 0.0f; }

#pragma unroll
    for (int rep = 0; rep < 8; rep++) {
        int f   = t + rep * 256;
        int row = f >> 4;
        int dq  = f & 15;
        float4 v = *(const float4*)&Qg[(size_t)(qbase + row) * D_ + dq * 4];
        Qs[row * 65 + dq * 4 + 0] = v.x;
        Qs[row * 65 + dq * 4 + 1] = v.y;
        Qs[row * 65 + dq * 4 + 2] = v.z;
        Qs[row * 65 + dq * 4 + 3] = v.w;
    }

    float o[8][4];
#pragma unroll
    for (int i = 0; i < 8; i++)
#pragma unroll
        for (int j = 0; j < 4; j++) o[i][j] = 0.0f;

    const int kmax = 2 * qi + 1;
    for (int kj = 0; kj <= kmax; kj++) {
        const int kbase = kj * 64;
        __syncthreads();

#pragma unroll
        for (int rep = 0; rep < 4; rep++) {
            int f   = t + rep * 256;
            int row = f >> 4;
            int dq  = f & 15;
            float4 vk = *(const float4*)&Kg[(size_t)(kbase + row) * D_ + dq * 4];
            Ks[row * 65 + dq * 4 + 0] = vk.x;
            Ks[row * 65 + dq * 4 + 1] = vk.y;
            Ks[row * 65 + dq * 4 + 2] = vk.z;
            Ks[row * 65 + dq * 4 + 3] = vk.w;
            float4 vv = *(const float4*)&Vg[(size_t)(kbase + row) * D_ + dq * 4];
            *(float4*)&Vs[row * 68 + dq * 4] = vv;
        }
        __syncthreads();

        float s[8][4];
#pragma unroll
        for (int i = 0; i < 8; i++)
#pragma unroll
            for (int j = 0; j < 4; j++) s[i][j] = 0.0f;

#pragma unroll 8
        for (int d = 0; d < 64; d++) {
            float a[8], bk[4];
#pragma unroll
            for (int i = 0; i < 4; i++) {
                a[i]     = Qs[(ty * 4 + i) * 65 + d];
                a[i + 4] = Qs[(64 + ty * 4 + i) * 65 + d];
            }
#pragma unroll
            for (int j = 0; j < 4; j++) bk[j] = Ks[(tx * 4 + j) * 65 + d];
#pragma unroll
            for (int i = 0; i < 8; i++)
#pragma unroll
                for (int j = 0; j < 4; j++)
                    s[i][j] = fmaf(a[i], bk[j], s[i][j]);
        }

#pragma unroll
        for (int i = 0; i < 8; i++) {
            int rr = (i < 4) ? (ty * 4 + i) : (64 + ty * 4 + (i - 4));
            int rg = qbase + rr;
            float4 v;
            v.x = (kbase + tx * 4 + 0 > rg) ? -1e30f : s[i][0] * 0.125f;
            v.y = (kbase + tx * 4 + 1 > rg) ? -1e30f : s[i][1] * 0.125f;
            v.z = (kbase + tx * 4 + 2 > rg) ? -1e30f : s[i][2] * 0.125f;
            v.w = (kbase + tx * 4 + 3 > rg) ? -1e30f : s[i][3] * 0.125f;
            *(float4*)&sP[rr * 68 + tx * 4] = v;
        }
        __syncthreads();

        {
            int r = t >> 1, q = t & 1;
            float* rowp = &sP[r * 68 + q * 32];
            float lmax = -1e30f;
#pragma unroll
            for (int c = 0; c < 32; c++) lmax = fmaxf(lmax, rowp[c]);
            red[r * 2 + q] = lmax;
            __syncthreads();
            float m_old = m_s[r];
            float m_new = fmaxf(m_old, fmaxf(red[r * 2], red[r * 2 + 1]));
            float lsum = 0.0f;
#pragma unroll
            for (int c = 0; c < 32; c++) {
                float p = __expf(rowp[c] - m_new);
                rowp[c] = p;
                lsum += p;
            }
            __syncthreads();
            red[r * 2 + q] = lsum;
            if (q == 0) corr_s[r] = __expf(m_old - m_new);
            __syncthreads();
            if (q == 0) {
                l_s[r] = l_s[r] * corr_s[r] + red[r * 2] + red[r * 2 + 1];
                m_s[r] = m_new;
            }
        }

#pragma unroll
        for (int i = 0; i < 8; i++) {
            int rr = (i < 4) ? (ty * 4 + i) : (64 + ty * 4 + (i - 4));
            float cr = corr_s[rr];
#pragma unroll
            for (int j = 0; j < 4; j++) o[i][j] *= cr;
        }

#pragma unroll 8
        for (int j0 = 0; j0 < 64; j0++) {
            float a[8];
#pragma unroll
            for (int i = 0; i < 4; i++) {
                a[i]     = sP[(ty * 4 + i) * 68 + j0];
                a[i + 4] = sP[(64 + ty * 4 + i) * 68 + j0];
            }
            float4 bv = *(const float4*)&Vs[j0 * 68 + tx * 4];
#pragma unroll
            for (int i = 0; i < 8; i++) {
                o[i][0] = fmaf(a[i], bv.x, o[i][0]);
                o[i][1] = fmaf(a[i], bv.y, o[i][1]);
                o[i][2] = fmaf(a[i], bv.z, o[i][2]);
                o[i][3] = fmaf(a[i], bv.w, o[i][3]);
            }
        }
    }

    __syncthreads();

    const int b = bh >> 4;
    const int h = bh & 15;
#pragma unroll
    for (int i = 0; i < 8; i++) {
        int rr  = (i < 4) ? (ty * 4 + i) : (64 + ty * 4 + (i - 4));
        float inv = 1.0f / l_s[rr];
        int tg  = qbase + rr;
        float4 v = make_float4(o[i][0] * inv, o[i][1] * inv,
                               o[i][2] * inv, o[i][3] * inv);
        *(float4*)&Y[((size_t)b * T_ + tg) * C_ + h * 64 + tx * 4] = v;
    }
}

// ---------------------------------------------------------------------------
extern "C" void kernel_launch(void* const* d_in, const int* in_sizes, int n_in,
                              void* d_out, int out_size)
{
    const float* X  = (const float*)d_in[0];
    const float* Wq = (const float*)d_in[1];
    const float* Wk = (const float*)d_in[2];
    const float* Wv = (const float*)d_in[3];
    const float* Wo = (const float*)d_in[4];
    const float* bo = (const float*)d_in[5];
    float* out = (float*)d_out;

    float *qp, *kp, *vp, *yp;
    __nv_bfloat16 *xh, *xl, *wh, *wl, *woh, *wol, *yh, *yl;
    cudaGetSymbolAddress((void**)&qp, g_Q);
    cudaGetSymbolAddress((void**)&kp, g_K);
    cudaGetSymbolAddress((void**)&vp, g_V);
    cudaGetSymbolAddress((void**)&yp, g_Y);
    cudaGetSymbolAddress((void**)&xh, g_Xhi);
    cudaGetSymbolAddress((void**)&xl, g_Xlo);
    cudaGetSymbolAddress((void**)&wh, g_Wh);
    cudaGetSymbolAddress((void**)&wl, g_Wl);
    cudaGetSymbolAddress((void**)&woh, g_Wohi);
    cudaGetSymbolAddress((void**)&wol, g_Wolo);
    cudaGetSymbolAddress((void**)&yh, g_Yhi);
    cudaGetSymbolAddress((void**)&yl, g_Ylo);

    // hi/lo split converts
    cvt_kernel<<<(M_ * C_ / 4 + 255) / 256, 256>>>(X, xh, xl, M_ * C_ / 4);
    cvt_kernel<<<(C_ * C_ / 4 + 255) / 256, 256>>>(Wq, wh,               wl,               C_ * C_ / 4);
    cvt_kernel<<<(C_ * C_ / 4 + 255) / 256, 256>>>(Wk, wh + C_ * C_,     wl + C_ * C_,     C_ * C_ / 4);
    cvt_kernel<<<(C_ * C_ / 4 + 255) / 256, 256>>>(Wv, wh + 2 * C_ * C_, wl + 2 * C_ * C_, C_ * C_ / 4);
    cvt_kernel<<<(C_ * C_ / 4 + 255) / 256, 256>>>(Wo, woh, wol, C_ * C_ / 4);

    // QKV projections (HMMA, fused across z), 64KB dynamic smem
    const int smem_tc = 2 * STAGE_B;
    cudaFuncSetAttribute((const void*)tc_gemm_qkv,
                         cudaFuncAttributeMaxDynamicSharedMemorySize, smem_tc);
    tc_gemm_qkv<<<dim3(C_ / 128, M_ / 128, 3), 256, smem_tc>>>(xh, xl, wh, wl, qp, kp, vp);

    // Attention (fp32)
    const size_t smem_at = (size_t)(128 * 65 + 64 * 65 + 64 * 68 + 128 * 68 +
                                    128 * 3 + 256) * sizeof(float);
    cudaFuncSetAttribute((const void*)attn_kernel,
                         cudaFuncAttributeMaxDynamicSharedMemorySize, (int)smem_at);
    attn_kernel<<<dim3(T_ / 128, B_ * H_), 256, smem_at>>>(yp);

    // Output projection (HMMA)
    cvt_kernel<<<(M_ * C_ / 4 + 255) / 256, 256>>>(yp, yh, yl, M_ * C_ / 4);
    cudaFuncSetAttribute((const void*)tc_gemm_out,
                         cudaFuncAttributeMaxDynamicSharedMemorySize, smem_tc);
    tc_gemm_out<<<dim3(C_ / 128, M_ / 128), 256, smem_tc>>>(yh, yl, woh, wol, bo, out);
}

// round 8
// speedup vs baseline: 2.7108x; 1.7823x over previous
#include <cuda_runtime.h>
#include <cuda_bf16.h>
#include <cstdint>

// Problem constants
#define B_ 4
#define T_ 2048
#define C_ 1024
#define H_ 16
#define D_ 64
#define M_ (B_ * T_)   // 8192 rows

// ---------------------------------------------------------------------------
// Scratch (allocation-free rule: __device__ globals)
// ---------------------------------------------------------------------------
__device__ float g_Y[(size_t)M_ * C_];             // attention out [b*T+t, h*D+d]

__device__ __align__(16) __nv_bfloat16 g_Xhi[(size_t)M_ * C_];
__device__ __align__(16) __nv_bfloat16 g_Xlo[(size_t)M_ * C_];
__device__ __align__(16) __nv_bfloat16 g_Wh[(size_t)3 * C_ * C_];
__device__ __align__(16) __nv_bfloat16 g_Wl[(size_t)3 * C_ * C_];
__device__ __align__(16) __nv_bfloat16 g_Wohi[(size_t)C_ * C_];
__device__ __align__(16) __nv_bfloat16 g_Wolo[(size_t)C_ * C_];
__device__ __align__(16) __nv_bfloat16 g_Yhi[(size_t)M_ * C_];
__device__ __align__(16) __nv_bfloat16 g_Ylo[(size_t)M_ * C_];
// Q/K/V in bf16 hi/lo, [b,h,t,d]
__device__ __align__(16) __nv_bfloat16 g_Qhi[(size_t)B_ * H_ * T_ * D_];
__device__ __align__(16) __nv_bfloat16 g_Qlo[(size_t)B_ * H_ * T_ * D_];
__device__ __align__(16) __nv_bfloat16 g_Khi[(size_t)B_ * H_ * T_ * D_];
__device__ __align__(16) __nv_bfloat16 g_Klo[(size_t)B_ * H_ * T_ * D_];
__device__ __align__(16) __nv_bfloat16 g_Vhi[(size_t)B_ * H_ * T_ * D_];
__device__ __align__(16) __nv_bfloat16 g_Vlo[(size_t)B_ * H_ * T_ * D_];

// ---------------------------------------------------------------------------
// Helpers
// ---------------------------------------------------------------------------
__device__ __forceinline__ uint32_t smem_u32(const void* p) {
    uint32_t a;
    asm("{ .reg .u64 t; cvta.to.shared.u64 t, %1; cvt.u32.u64 %0, t; }"
        : "=r"(a) : "l"(p));
    return a;
}

#define CP_ASYNC16(dst, src) \
    asm volatile("cp.async.cg.shared.global [%0], [%1], 16;" \
                 :: "r"(dst), "l"(src) : "memory")
#define CP_COMMIT()  asm volatile("cp.async.commit_group;" ::: "memory")
#define CP_WAIT(n)   asm volatile("cp.async.wait_group %0;" :: "n"(n) : "memory")

#define LDSM_X4(r0, r1, r2, r3, addr) \
    asm volatile("ldmatrix.sync.aligned.m8n8.x4.shared.b16 {%0,%1,%2,%3}, [%4];" \
                 : "=r"(r0), "=r"(r1), "=r"(r2), "=r"(r3) : "r"(addr))

#define LDSM_X4_T(r0, r1, r2, r3, addr) \
    asm volatile("ldmatrix.sync.aligned.m8n8.x4.trans.shared.b16 {%0,%1,%2,%3}, [%4];" \
                 : "=r"(r0), "=r"(r1), "=r"(r2), "=r"(r3) : "r"(addr))

#define MMA16816(d, a, b0, b1) \
    asm volatile("mma.sync.aligned.m16n8k16.row.col.f32.bf16.bf16.f32 " \
                 "{%0,%1,%2,%3}, {%4,%5,%6,%7}, {%8,%9}, {%0,%1,%2,%3};" \
                 : "+f"((d)[0]), "+f"((d)[1]), "+f"((d)[2]), "+f"((d)[3]) \
                 : "r"((a)[0]), "r"((a)[1]), "r"((a)[2]), "r"((a)[3]), \
                   "r"(b0), "r"(b1))

__device__ __forceinline__ uint32_t pack2(__nv_bfloat16 a, __nv_bfloat16 b) {
    __nv_bfloat162 v = __halves2bfloat162(a, b);   // x=a (elem k), y=b (elem k+1)
    return *reinterpret_cast<uint32_t*>(&v);
}

// ---------------------------------------------------------------------------
// fp32 -> bf16 hi/lo split
// ---------------------------------------------------------------------------
__global__ __launch_bounds__(256)
void cvt_kernel(const float* __restrict__ in, __nv_bfloat16* __restrict__ hi,
                __nv_bfloat16* __restrict__ lo, int n4)
{
    int i = blockIdx.x * 256 + threadIdx.x;
    if (i >= n4) return;
    float4 v = ((const float4*)in)[i];
    __nv_bfloat16 h0 = __float2bfloat16_rn(v.x);
    __nv_bfloat16 h1 = __float2bfloat16_rn(v.y);
    __nv_bfloat16 h2 = __float2bfloat16_rn(v.z);
    __nv_bfloat16 h3 = __float2bfloat16_rn(v.w);
    __nv_bfloat16 l0 = __float2bfloat16_rn(v.x - __bfloat162float(h0));
    __nv_bfloat16 l1 = __float2bfloat16_rn(v.y - __bfloat162float(h1));
    __nv_bfloat16 l2 = __float2bfloat16_rn(v.z - __bfloat162float(h2));
    __nv_bfloat16 l3 = __float2bfloat16_rn(v.w - __bfloat162float(h3));
    ((__nv_bfloat162*)hi)[2 * i]     = __halves2bfloat162(h0, h1);
    ((__nv_bfloat162*)hi)[2 * i + 1] = __halves2bfloat162(h2, h3);
    ((__nv_bfloat162*)lo)[2 * i]     = __halves2bfloat162(l0, l1);
    ((__nv_bfloat162*)lo)[2 * i + 1] = __halves2bfloat162(l2, l3);
}

// ---------------------------------------------------------------------------
// HMMA bf16 GEMM (extended-K hi/lo split), 128x128 tile, BK=64, 8 warps.
// MODE 0: fp32 [M,N] + bias.   MODE 1: bf16 hi/lo split-head [b,h,t,d].
// ---------------------------------------------------------------------------
#define NKCH 48
#define STAGE_B 32768

__device__ __forceinline__
void issue_chunk(uint32_t sbase, const __nv_bfloat16* __restrict__ Aseg,
                 const __nv_bfloat16* __restrict__ Bseg,
                 int m0, int n0, int k_in, int t)
{
#pragma unroll
    for (int rep = 0; rep < 4; rep++) {
        int idx = t + rep * 256;
        int r = idx >> 3, s = idx & 7;
        uint32_t dstA = sbase + r * 128 + ((s ^ (r & 7)) << 4);
        const void* srcA = Aseg + (size_t)(m0 + r) * C_ + k_in + s * 8;
        CP_ASYNC16(dstA, srcA);
        const void* srcB = Bseg + (size_t)(n0 + r) * C_ + k_in + s * 8;
        CP_ASYNC16(dstA + 16384, srcB);
    }
}

template <int MODE>
__device__ __forceinline__
void hmma_gemm_body(const __nv_bfloat16* __restrict__ Ahi,
                    const __nv_bfloat16* __restrict__ Alo,
                    const __nv_bfloat16* __restrict__ Whi,
                    const __nv_bfloat16* __restrict__ Wlo,
                    const float* __restrict__ bias, float* __restrict__ out,
                    __nv_bfloat16* __restrict__ ohi, __nv_bfloat16* __restrict__ olo)
{
    extern __shared__ __align__(128) char sm[];
    const uint32_t sm0 = smem_u32(sm);
    const int t    = threadIdx.x;
    const int lane = t & 31;
    const int w    = t >> 5;
    const int wm   = w & 3;
    const int wn   = w >> 2;
    const int m0   = blockIdx.y * 128;
    const int n0   = blockIdx.x * 128;

    const int l4 = lane >> 4;
    uint32_t baseA[2], baseB[4];
#pragma unroll
    for (int mt = 0; mt < 2; mt++) {
        int m_l = wm * 32 + mt * 16 + ((lane >> 3) & 1) * 8 + (lane & 7);
        baseA[mt] = m_l * 128 + (((m_l & 7) ^ l4) << 4);
    }
#pragma unroll
    for (int j = 0; j < 4; j++) {
        int n_l = wn * 64 + j * 16 + ((lane >> 3) & 1) * 8 + (lane & 7);
        baseB[j] = 16384 + n_l * 128 + (((n_l & 7) ^ l4) << 4);
    }

    float acc[2][8][4];
#pragma unroll
    for (int mt = 0; mt < 2; mt++)
#pragma unroll
        for (int nt = 0; nt < 8; nt++)
#pragma unroll
            for (int e = 0; e < 4; e++) acc[mt][nt][e] = 0.0f;

    issue_chunk(sm0, Ahi, Whi, m0, n0, 0, t);
    CP_COMMIT();

    for (int kc = 0; kc < NKCH; kc++) {
        __syncthreads();
        if (kc + 1 < NKCH) {
            int kn = kc + 1;
            const __nv_bfloat16* Aseg = (kn < 32) ? Ahi : Alo;
            const __nv_bfloat16* Bseg = (kn < 16) ? Whi : (kn < 32 ? Wlo : Whi);
            issue_chunk(sm0 + ((kn & 1) ? STAGE_B : 0), Aseg, Bseg,
                        m0, n0, (kn & 15) * 64, t);
            CP_COMMIT();
            CP_WAIT(1);
        } else {
            CP_WAIT(0);
        }
        __syncthreads();

        const uint32_t sbase = sm0 + ((kc & 1) ? STAGE_B : 0);
#pragma unroll
        for (int kk = 0; kk < 4; kk++) {
            uint32_t a[2][4], b[4][4];
#pragma unroll
            for (int mt = 0; mt < 2; mt++)
                LDSM_X4(a[mt][0], a[mt][1], a[mt][2], a[mt][3],
                        sbase + (baseA[mt] ^ (kk << 5)));
#pragma unroll
            for (int j = 0; j < 4; j++)
                LDSM_X4(b[j][0], b[j][1], b[j][2], b[j][3],
                        sbase + (baseB[j] ^ (kk << 5)));
#pragma unroll
            for (int mt = 0; mt < 2; mt++)
#pragma unroll
                for (int nt = 0; nt < 8; nt++)
                    MMA16816(acc[mt][nt], a[mt],
                             b[nt >> 1][nt & 1], b[nt >> 1][(nt & 1) + 2]);
        }
    }

    const int qrow = lane >> 2;
    const int qcol = (lane & 3) * 2;
#pragma unroll
    for (int mt = 0; mt < 2; mt++) {
#pragma unroll
        for (int half = 0; half < 2; half++) {
            const int grow = m0 + wm * 32 + mt * 16 + half * 8 + qrow;
#pragma unroll
            for (int nt = 0; nt < 8; nt++) {
                const int gcol = n0 + wn * 64 + nt * 8 + qcol;
                float2 v = make_float2(acc[mt][nt][half * 2],
                                       acc[mt][nt][half * 2 + 1]);
                if (MODE == 0) {
                    v.x += bias[gcol];
                    v.y += bias[gcol + 1];
                    *(float2*)&out[(size_t)grow * C_ + gcol] = v;
                } else {
                    const int head = gcol >> 6, d = gcol & 63;
                    const int bb = grow >> 11, tt = grow & (T_ - 1);
                    size_t idx = (((size_t)bb * H_ + head) * T_ + tt) * D_ + d;
                    __nv_bfloat16 h0 = __float2bfloat16_rn(v.x);
                    __nv_bfloat16 h1 = __float2bfloat16_rn(v.y);
                    __nv_bfloat16 l0 = __float2bfloat16_rn(v.x - __bfloat162float(h0));
                    __nv_bfloat16 l1 = __float2bfloat16_rn(v.y - __bfloat162float(h1));
                    *(__nv_bfloat162*)&ohi[idx] = __halves2bfloat162(h0, h1);
                    *(__nv_bfloat162*)&olo[idx] = __halves2bfloat162(l0, l1);
                }
            }
        }
    }
}

__global__ __launch_bounds__(256)
void tc_gemm_qkv(const __nv_bfloat16* __restrict__ Xhi,
                 const __nv_bfloat16* __restrict__ Xlo,
                 const __nv_bfloat16* __restrict__ Wh,
                 const __nv_bfloat16* __restrict__ Wl,
                 __nv_bfloat16* __restrict__ Qh, __nv_bfloat16* __restrict__ Ql,
                 __nv_bfloat16* __restrict__ Kh, __nv_bfloat16* __restrict__ Kl,
                 __nv_bfloat16* __restrict__ Vh, __nv_bfloat16* __restrict__ Vl)
{
    const int z = blockIdx.z;
    const __nv_bfloat16* wh = Wh + (size_t)z * C_ * C_;
    const __nv_bfloat16* wl = Wl + (size_t)z * C_ * C_;
    __nv_bfloat16* oh = (z == 0) ? Qh : (z == 1) ? Kh : Vh;
    __nv_bfloat16* ol = (z == 0) ? Ql : (z == 1) ? Kl : Vl;
    hmma_gemm_body<1>(Xhi, Xlo, wh, wl, nullptr, nullptr, oh, ol);
}

__global__ __launch_bounds__(256)
void tc_gemm_out(const __nv_bfloat16* __restrict__ Yhi,
                 const __nv_bfloat16* __restrict__ Ylo,
                 const __nv_bfloat16* __restrict__ Wh,
                 const __nv_bfloat16* __restrict__ Wl,
                 const float* __restrict__ bias, float* __restrict__ out)
{
    hmma_gemm_body<0>(Yhi, Ylo, Wh, Wl, bias, out, nullptr, nullptr);
}

// ---------------------------------------------------------------------------
// HMMA flash attention (causal). Block = 128 q-rows x (b*h). 8 warps, each
// owns a 16-row stripe (softmax fully warp-local). BKV=64, double-buffered
// cp.async K/V stages. hi/lo bf16 split (3 MMA terms) for S and P@V.
// smem: Qhi/Qlo 32KB + 2 stages x (Khi,Klo,Vhi,Vlo 8KB each) = 96KB.
// ---------------------------------------------------------------------------
#define ATT_SMEM 98304

__device__ __forceinline__
void issue_kv(uint32_t dstbase,
              const __nv_bfloat16* __restrict__ Kh, const __nv_bfloat16* __restrict__ Kl,
              const __nv_bfloat16* __restrict__ Vh, const __nv_bfloat16* __restrict__ Vl,
              int kbase, int t)
{
#pragma unroll
    for (int rep = 0; rep < 2; rep++) {
        int idx = t + rep * 256;   // 0..511
        int r = idx >> 3, c = idx & 7;
        uint32_t dst = dstbase + r * 128 + ((c ^ (r & 7)) << 4);
        size_t g = (size_t)(kbase + r) * D_ + c * 8;
        CP_ASYNC16(dst,          (const void*)(Kh + g));
        CP_ASYNC16(dst + 8192,   (const void*)(Kl + g));
        CP_ASYNC16(dst + 16384,  (const void*)(Vh + g));
        CP_ASYNC16(dst + 24576,  (const void*)(Vl + g));
    }
}

__global__ __launch_bounds__(256)
void attn_hmma(const __nv_bfloat16* __restrict__ Qhi, const __nv_bfloat16* __restrict__ Qlo,
               const __nv_bfloat16* __restrict__ Khi, const __nv_bfloat16* __restrict__ Klo,
               const __nv_bfloat16* __restrict__ Vhi, const __nv_bfloat16* __restrict__ Vlo,
               float* __restrict__ Y)
{
    extern __shared__ __align__(128) char sm[];
    const uint32_t s0 = smem_u32(sm);
    const int t = threadIdx.x, lane = t & 31, w = t >> 5;
    const int bh = blockIdx.y;
    const int qi = (int)(gridDim.x - 1 - blockIdx.x);   // big tiles first
    const int qbase = qi * 128;
    const size_t base = (size_t)bh * T_ * D_;
    const __nv_bfloat16* Qh = Qhi + base + (size_t)qbase * D_;
    const __nv_bfloat16* Ql = Qlo + base + (size_t)qbase * D_;
    const __nv_bfloat16* Kh = Khi + base;
    const __nv_bfloat16* Kl = Klo + base;
    const __nv_bfloat16* Vh = Vhi + base;
    const __nv_bfloat16* Vl = Vlo + base;

    // Q tiles -> smem [0, 32KB)
#pragma unroll
    for (int rep = 0; rep < 4; rep++) {
        int idx = t + rep * 256;
        int r = idx >> 3, c = idx & 7;
        uint32_t dst = s0 + r * 128 + ((c ^ (r & 7)) << 4);
        size_t g = (size_t)r * D_ + c * 8;
        CP_ASYNC16(dst,          (const void*)(Qh + g));
        CP_ASYNC16(dst + 16384,  (const void*)(Ql + g));
    }
    CP_COMMIT();

    const int nch = 2 * qi + 2;
    issue_kv(s0 + 32768, Kh, Kl, Vh, Vl, 0, t);
    CP_COMMIT();

    CP_WAIT(1);            // Q landed (KV0 may still be in flight)
    __syncthreads();

    // Q fragments (persistent in registers)
    uint32_t aQh[4][4], aQl[4][4];
#pragma unroll
    for (int s = 0; s < 4; s++) {
        int row = 16 * w + (lane & 15);
        int cb  = 2 * s + (lane >> 4);
        uint32_t ad = s0 + row * 128 + ((cb ^ (row & 7)) << 4);
        LDSM_X4(aQh[s][0], aQh[s][1], aQh[s][2], aQh[s][3], ad);
        LDSM_X4(aQl[s][0], aQl[s][1], aQl[s][2], aQl[s][3], ad + 16384);
    }

    float accO[8][4];
#pragma unroll
    for (int j = 0; j < 8; j++)
#pragma unroll
        for (int e = 0; e < 4; e++) accO[j][e] = 0.0f;

    float m0s = -1e30f, m1s = -1e30f, l0s = 0.0f, l1s = 0.0f;
    const int r0g = qbase + 16 * w + (lane >> 2);
    const int r1g = r0g + 8;

    for (int kc = 0; kc < nch; kc++) {
        const int kbase = kc * 64;
        const int stage = kc & 1;
        if (kc + 1 < nch) {
            issue_kv(s0 + 32768 + (stage ^ 1) * 32768, Kh, Kl, Vh, Vl, kbase + 64, t);
            CP_COMMIT();
            CP_WAIT(1);
        } else {
            CP_WAIT(0);
        }
        __syncthreads();
        const uint32_t kvb = s0 + 32768 + stage * 32768;

        if (kbase <= qbase + 16 * w + 15) {   // warp not fully masked
            // ---- S = Q @ K^T (16 x 64 per warp), 3-term split ----
            float sc[8][4];
#pragma unroll
            for (int j = 0; j < 8; j++)
#pragma unroll
                for (int e = 0; e < 4; e++) sc[j][e] = 0.0f;

#pragma unroll
            for (int s = 0; s < 4; s++) {
                uint32_t bKh[8][2], bKl[8][2];
#pragma unroll
                for (int jp = 0; jp < 4; jp++) {
                    int row = 16 * jp + ((lane >> 4) << 3) + (lane & 7);
                    int cb  = 2 * s + ((lane >> 3) & 1);
                    uint32_t ad = kvb + row * 128 + ((cb ^ (row & 7)) << 4);
                    LDSM_X4(bKh[2*jp][0], bKh[2*jp][1], bKh[2*jp+1][0], bKh[2*jp+1][1], ad);
                    LDSM_X4(bKl[2*jp][0], bKl[2*jp][1], bKl[2*jp+1][0], bKl[2*jp+1][1], ad + 8192);
                }
#pragma unroll
                for (int j = 0; j < 8; j++) {
                    MMA16816(sc[j], aQh[s], bKh[j][0], bKh[j][1]);
                    MMA16816(sc[j], aQh[s], bKl[j][0], bKl[j][1]);
                    MMA16816(sc[j], aQl[s], bKh[j][0], bKh[j][1]);
                }
            }

            // ---- scale + causal mask ----
            const int c0b = kbase + 2 * (lane & 3);
#pragma unroll
            for (int j = 0; j < 8; j++) {
                int cc = c0b + 8 * j;
                sc[j][0] = (cc     > r0g) ? -1e30f : sc[j][0] * 0.125f;
                sc[j][1] = (cc + 1 > r0g) ? -1e30f : sc[j][1] * 0.125f;
                sc[j][2] = (cc     > r1g) ? -1e30f : sc[j][2] * 0.125f;
                sc[j][3] = (cc + 1 > r1g) ? -1e30f : sc[j][3] * 0.125f;
            }

            // ---- online softmax (warp-local, quad-lane reduction) ----
            float mx0 = -1e30f, mx1 = -1e30f;
#pragma unroll
            for (int j = 0; j < 8; j++) {
                mx0 = fmaxf(mx0, fmaxf(sc[j][0], sc[j][1]));
                mx1 = fmaxf(mx1, fmaxf(sc[j][2], sc[j][3]));
            }
            mx0 = fmaxf(mx0, __shfl_xor_sync(0xffffffffu, mx0, 1));
            mx0 = fmaxf(mx0, __shfl_xor_sync(0xffffffffu, mx0, 2));
            mx1 = fmaxf(mx1, __shfl_xor_sync(0xffffffffu, mx1, 1));
            mx1 = fmaxf(mx1, __shfl_xor_sync(0xffffffffu, mx1, 2));
            float mn0 = fmaxf(m0s, mx0), mn1 = fmaxf(m1s, mx1);
            float cr0 = __expf(m0s - mn0), cr1 = __expf(m1s - mn1);
            m0s = mn0; m1s = mn1;

            float sum0 = 0.0f, sum1 = 0.0f;
            uint32_t aPh[4][4], aPl[4][4];
#pragma unroll
            for (int jp = 0; jp < 4; jp++) {
#pragma unroll
                for (int u = 0; u < 2; u++) {
                    int j = 2 * jp + u;
                    float p0 = __expf(sc[j][0] - mn0);
                    float p1 = __expf(sc[j][1] - mn0);
                    float p2 = __expf(sc[j][2] - mn1);
                    float p3 = __expf(sc[j][3] - mn1);
                    sum0 += p0 + p1;
                    sum1 += p2 + p3;
                    __nv_bfloat16 h0 = __float2bfloat16_rn(p0);
                    __nv_bfloat16 h1 = __float2bfloat16_rn(p1);
                    __nv_bfloat16 h2 = __float2bfloat16_rn(p2);
                    __nv_bfloat16 h3 = __float2bfloat16_rn(p3);
                    aPh[jp][2*u]     = pack2(h0, h1);
                    aPh[jp][2*u + 1] = pack2(h2, h3);
                    aPl[jp][2*u]     = pack2(__float2bfloat16_rn(p0 - __bfloat162float(h0)),
                                             __float2bfloat16_rn(p1 - __bfloat162float(h1)));
                    aPl[jp][2*u + 1] = pack2(__float2bfloat16_rn(p2 - __bfloat162float(h2)),
                                             __float2bfloat16_rn(p3 - __bfloat162float(h3)));
                }
            }
            sum0 += __shfl_xor_sync(0xffffffffu, sum0, 1);
            sum0 += __shfl_xor_sync(0xffffffffu, sum0, 2);
            sum1 += __shfl_xor_sync(0xffffffffu, sum1, 1);
            sum1 += __shfl_xor_sync(0xffffffffu, sum1, 2);
            l0s = l0s * cr0 + sum0;
            l1s = l1s * cr1 + sum1;

            // ---- rescale O, then O += P @ V (3-term split) ----
#pragma unroll
            for (int j = 0; j < 8; j++) {
                accO[j][0] *= cr0; accO[j][1] *= cr0;
                accO[j][2] *= cr1; accO[j][3] *= cr1;
            }

#pragma unroll
            for (int s = 0; s < 4; s++) {
                uint32_t bVh[8][2], bVl[8][2];
#pragma unroll
                for (int jp = 0; jp < 4; jp++) {
                    int row = 16 * s + ((lane >> 3) & 1) * 8 + (lane & 7);
                    int cb  = 2 * jp + (lane >> 4);
                    uint32_t ad = kvb + 16384 + row * 128 + ((cb ^ (row & 7)) << 4);
                    LDSM_X4_T(bVh[2*jp][0], bVh[2*jp][1], bVh[2*jp+1][0], bVh[2*jp+1][1], ad);
                    LDSM_X4_T(bVl[2*jp][0], bVl[2*jp][1], bVl[2*jp+1][0], bVl[2*jp+1][1], ad + 8192);
                }
#pragma unroll
                for (int j = 0; j < 8; j++) {
                    MMA16816(accO[j], aPh[s], bVh[j][0], bVh[j][1]);
                    MMA16816(accO[j], aPh[s], bVl[j][0], bVl[j][1]);
                    MMA16816(accO[j], aPl[s], bVh[j][0], bVh[j][1]);
                }
            }
        }
        __syncthreads();   // all warps done with this stage before it is refilled
    }

    // ---- normalize + store ----
    const float i0 = 1.0f / l0s, i1 = 1.0f / l1s;
    const int b = bh >> 4, h = bh & 15;
    float* y0 = Y + ((size_t)b * T_ + r0g) * C_ + h * 64 + 2 * (lane & 3);
    float* y1 = Y + ((size_t)b * T_ + r1g) * C_ + h * 64 + 2 * (lane & 3);
#pragma unroll
    for (int j = 0; j < 8; j++) {
        *(float2*)(y0 + 8 * j) = make_float2(accO[j][0] * i0, accO[j][1] * i0);
        *(float2*)(y1 + 8 * j) = make_float2(accO[j][2] * i1, accO[j][3] * i1);
    }
}

// ---------------------------------------------------------------------------
extern "C" void kernel_launch(void* const* d_in, const int* in_sizes, int n_in,
                              void* d_out, int out_size)
{
    const float* X  = (const float*)d_in[0];
    const float* Wq = (const float*)d_in[1];
    const float* Wk = (const float*)d_in[2];
    const float* Wv = (const float*)d_in[3];
    const float* Wo = (const float*)d_in[4];
    const float* bo = (const float*)d_in[5];
    float* out = (float*)d_out;

    float* yp;
    __nv_bfloat16 *xh, *xl, *wh, *wl, *woh, *wol, *yh, *yl;
    __nv_bfloat16 *qh, *ql, *kh, *kl, *vh, *vl;
    cudaGetSymbolAddress((void**)&yp, g_Y);
    cudaGetSymbolAddress((void**)&xh, g_Xhi);
    cudaGetSymbolAddress((void**)&xl, g_Xlo);
    cudaGetSymbolAddress((void**)&wh, g_Wh);
    cudaGetSymbolAddress((void**)&wl, g_Wl);
    cudaGetSymbolAddress((void**)&woh, g_Wohi);
    cudaGetSymbolAddress((void**)&wol, g_Wolo);
    cudaGetSymbolAddress((void**)&yh, g_Yhi);
    cudaGetSymbolAddress((void**)&yl, g_Ylo);
    cudaGetSymbolAddress((void**)&qh, g_Qhi);
    cudaGetSymbolAddress((void**)&ql, g_Qlo);
    cudaGetSymbolAddress((void**)&kh, g_Khi);
    cudaGetSymbolAddress((void**)&kl, g_Klo);
    cudaGetSymbolAddress((void**)&vh, g_Vhi);
    cudaGetSymbolAddress((void**)&vl, g_Vlo);

    // hi/lo split converts
    cvt_kernel<<<(M_ * C_ / 4 + 255) / 256, 256>>>(X, xh, xl, M_ * C_ / 4);
    cvt_kernel<<<(C_ * C_ / 4 + 255) / 256, 256>>>(Wq, wh,               wl,               C_ * C_ / 4);
    cvt_kernel<<<(C_ * C_ / 4 + 255) / 256, 256>>>(Wk, wh + C_ * C_,     wl + C_ * C_,     C_ * C_ / 4);
    cvt_kernel<<<(C_ * C_ / 4 + 255) / 256, 256>>>(Wv, wh + 2 * C_ * C_, wl + 2 * C_ * C_, C_ * C_ / 4);
    cvt_kernel<<<(C_ * C_ / 4 + 255) / 256, 256>>>(Wo, woh, wol, C_ * C_ / 4);

    // QKV projections (HMMA, fused across z) -> bf16 hi/lo split-head
    const int smem_tc = 2 * STAGE_B;
    cudaFuncSetAttribute((const void*)tc_gemm_qkv,
                         cudaFuncAttributeMaxDynamicSharedMemorySize, smem_tc);
    tc_gemm_qkv<<<dim3(C_ / 128, M_ / 128, 3), 256, smem_tc>>>(
        xh, xl, wh, wl, qh, ql, kh, kl, vh, vl);

    // Attention (HMMA flash)
    cudaFuncSetAttribute((const void*)attn_hmma,
                         cudaFuncAttributeMaxDynamicSharedMemorySize, ATT_SMEM);
    attn_hmma<<<dim3(T_ / 128, B_ * H_), 256, ATT_SMEM>>>(qh, ql, kh, kl, vh, vl, yp);

    // Output projection (HMMA)
    cvt_kernel<<<(M_ * C_ / 4 + 255) / 256, 256>>>(yp, yh, yl, M_ * C_ / 4);
    cudaFuncSetAttribute((const void*)tc_gemm_out,
                         cudaFuncAttributeMaxDynamicSharedMemorySize, smem_tc);
    tc_gemm_out<<<dim3(C_ / 128, M_ / 128), 256, smem_tc>>>(yh, yl, woh, wol, bo, out);
}